// round 9
// baseline (speedup 1.0000x reference)
#include <cuda_runtime.h>
#include <cuda_bf16.h>

// Problem constants (fixed by the reference)
#define GRID_NX   48
#define GRID_NY   48
#define GRID_NZ   48
#define N_GRID    (GRID_NX * GRID_NY * GRID_NZ)   // 110592
#define SPACING   0.5f
#define A_MAX     800
#define NG        6
#define MAX_PAIRS (A_MAX * NG)                    // 4800

// Cull threshold: drop pair for a tile when |c|*min_d2 > T  (contribution < 2^-18 * w)
#define T_CUT     18.0f

// Tile geometry: 8 x 8 x 4 grid points per tile (432 tiles)
#define TILE_X 8
#define TILE_Y 8
#define TILE_Z 4
#define NBX (GRID_NX / TILE_X)   // 6
#define NBY (GRID_NY / TILE_Y)   // 6
#define NBZ (GRID_NZ / TILE_Z)   // 12
#define N_TILES (NBX * NBY * NBZ)

#define NWARP  8                 // pair-range partitions (one warp each)
#define CHUNK  32                // pairs culled per warp-chunk (one ballot)

// Scratch (__device__ globals, no allocation)
__device__ float4 g_cull[MAX_PAIRS];        // px, py, pz, d2cut (-1 => inactive)
// Separable 1-D tables. g_exp is PAIRED layout per x-tile:
//   g_exp[p][tile*8 + slot*2 + half] = Ex(tile*8 + slot + 4*half)
// so 4 consecutive ulonglongs per tile == (Ex(i), Ex(i+4)) for i=0..3,
// matching the packed accumulator layout accp_i = (x_i, x_{i+4}).
__device__ float g_exp[MAX_PAIRS][48];      // Ex, paired layout
__device__ float g_eyw[MAX_PAIRS][48];      // w * Ey
__device__ float g_ez [MAX_PAIRS][48];      // Ez

__device__ __forceinline__ float ex2f(float x) {
    float r;
    asm("ex2.approx.f32 %0, %1;" : "=f"(r) : "f"(x));
    return r;
}

// Packed f32x2 helpers (Blackwell)
__device__ __forceinline__ unsigned long long pk(float lo, float hi) {
    unsigned long long r;
    asm("mov.b64 %0, {%1, %2};" : "=l"(r) : "f"(lo), "f"(hi));
    return r;
}
__device__ __forceinline__ void unpk(float& lo, float& hi, unsigned long long v) {
    asm("mov.b64 {%0, %1}, %2;" : "=f"(lo), "=f"(hi) : "l"(v));
}
__device__ __forceinline__ unsigned long long fma2(unsigned long long a,
                                                   unsigned long long b,
                                                   unsigned long long c) {
    unsigned long long r;
    asm("fma.rn.f32x2 %0, %1, %2, %3;" : "=l"(r) : "l"(a), "l"(b), "l"(c));
    return r;
}

// ---------------------------------------------------------------------------
// Kernel 1: build cull table + separable 1-D exp tables.
// One thread per (pair, grid index i48): 3 EX2 per thread, fully parallel.
// Thread with i48==0 also writes the pair's cull entry.
// ---------------------------------------------------------------------------
__global__ __launch_bounds__(256)
void build_tables(const float* __restrict__ X,
                  const float* __restrict__ aw,
                  const float* __restrict__ bw,
                  const int*   __restrict__ elements,
                  const int*   __restrict__ C_expand,
                  int npairs)
{
    const float LOG2E = 1.4426950408889634f;
    int t = blockIdx.x * 256 + threadIdx.x;
    int p   = t / 48;
    int i48 = t % 48;
    if (p >= npairs) return;
    int a = p / NG;

    float c = bw[p] * LOG2E;          // c < 0
    float w = aw[p];
    float px = X[a * 3 + 0];
    float py = X[a * 3 + 1];
    float pz = X[a * 3 + 2];

    float g = (float)i48 * SPACING;
    float dx = g - px, dy = g - py, dz = g - pz;

    // Ex in paired layout
    int tile = i48 >> 3, ii = i48 & 7;
    int slot = ii & 3, half = ii >> 2;
    g_exp[p][tile * 8 + slot * 2 + half] = ex2f(c * dx * dx);
    g_eyw[p][i48] = w * ex2f(c * dy * dy);
    g_ez [p][i48] = ex2f(c * dz * dz);

    if (i48 == 0) {
        bool act = (elements[a] != 5) && (C_expand[a] == 1);
        g_cull[p] = make_float4(px, py, pz, act ? (T_CUT / (-c)) : -1.0f);
    }
}

// ---------------------------------------------------------------------------
// Kernel 2: density. One 256-thread block per tile; warp w handles pair
// eighth w independently: cull (AABB vs per-pair radius) -> stage survivor
// table slices into shared -> accumulate with PURE packed FMAs:
//   acc_i += (w*Ey(ty) * Ez(tz)) * ExPair_i        (4 x fma.rn.f32x2)
// No EX2 in the inner loop at all. Deterministic fixed-order reduction.
// ---------------------------------------------------------------------------
__global__ __launch_bounds__(256)
void density_kernel(int npairs, float* __restrict__ out)
{
    __shared__ float s_ex[NWARP][CHUNK][8];           // paired Ex (4 ulonglong)
    __shared__ float s_ey[NWARP][CHUNK][8];           // w*Ey for tile rows
    __shared__ float s_ez[NWARP][CHUNK][4];           // Ez for tile planes
    __shared__ float s_acc[NWARP][32][TILE_X + 1];    // +1: bank padding

    int tid  = threadIdx.x;
    int lane = tid & 31;
    int wid  = tid >> 5;
    int bid  = blockIdx.x;
    int bx = bid % NBX;
    int by = (bid / NBX) % NBY;
    int bz = bid / (NBX * NBY);

    // Tile AABB in real coordinates
    float x_lo = (float)(bx * TILE_X) * SPACING;
    float y_lo = (float)(by * TILE_Y) * SPACING;
    float z_lo = (float)(bz * TILE_Z) * SPACING;
    float x_hi = x_lo + (float)(TILE_X - 1) * SPACING;
    float y_hi = y_lo + (float)(TILE_Y - 1) * SPACING;
    float z_hi = z_lo + (float)(TILE_Z - 1) * SPACING;

    // This lane's x-row: lane -> (ty in 0..7, tz in 0..3)
    int ty = lane & 7;
    int tz = lane >> 3;

    // This warp's pair range
    int p_beg = (npairs * wid) / NWARP;
    int p_end = (npairs * (wid + 1)) / NWARP;

    // Packed accumulators: accp[i] = (sum @ x_i, sum @ x_{i+4})
    unsigned long long accp0 = 0ull, accp1 = 0ull, accp2 = 0ull, accp3 = 0ull;

    for (int c0 = p_beg; c0 < p_end; c0 += CHUNK) {
        int cend = p_end - c0;
        if (cend > CHUNK) cend = CHUNK;

        // ---- Cull one 32-pair chunk + stage survivor slices into shared
        int j = c0 + lane;
        bool sv = false;
        if (lane < cend) {
            float4 cd = g_cull[j];
            float dx = fmaxf(fmaxf(x_lo - cd.x, cd.x - x_hi), 0.0f);
            float dy = fmaxf(fmaxf(y_lo - cd.y, cd.y - y_hi), 0.0f);
            float dz = fmaxf(fmaxf(z_lo - cd.z, cd.z - z_hi), 0.0f);
            float md2 = fmaf(dx, dx, fmaf(dy, dy, dz * dz));
            sv = (md2 <= cd.w);
        }
        unsigned m = __ballot_sync(0xffffffffu, sv);
        int nsurv = __popc(m);
        if (sv) {
            int pos = __popc(m & ((1u << lane) - 1u));
            const float4* ex = reinterpret_cast<const float4*>(&g_exp[j][bx * 8]);
            const float4* ey = reinterpret_cast<const float4*>(&g_eyw[j][by * 8]);
            const float4* ez = reinterpret_cast<const float4*>(&g_ez [j][bz * 4]);
            reinterpret_cast<float4*>(s_ex[wid][pos])[0] = ex[0];
            reinterpret_cast<float4*>(s_ex[wid][pos])[1] = ex[1];
            reinterpret_cast<float4*>(s_ey[wid][pos])[0] = ey[0];
            reinterpret_cast<float4*>(s_ey[wid][pos])[1] = ey[1];
            reinterpret_cast<float4*>(s_ez[wid][pos])[0] = ez[0];
        }
        __syncwarp();

        // ---- Accumulate: pure packed FMAs, no EX2
        for (int s = 0; s < nsurv; s++) {
            float eyz = s_ey[wid][s][ty] * s_ez[wid][s][tz];
            unsigned long long e2 = pk(eyz, eyz);
            const unsigned long long* exp =
                reinterpret_cast<const unsigned long long*>(s_ex[wid][s]);
            accp0 = fma2(exp[0], e2, accp0);
            accp1 = fma2(exp[1], e2, accp1);
            accp2 = fma2(exp[2], e2, accp2);
            accp3 = fma2(exp[3], e2, accp3);
        }
        __syncwarp();   // protect this warp's shared slices before refill
    }

    // ---- Deposit per-warp accumulators (unpacked)
    {
        float a0, a4, a1, a5, a2, a6, a3, a7;
        unpk(a0, a4, accp0);
        unpk(a1, a5, accp1);
        unpk(a2, a6, accp2);
        unpk(a3, a7, accp3);
        s_acc[wid][lane][0] = a0;
        s_acc[wid][lane][1] = a1;
        s_acc[wid][lane][2] = a2;
        s_acc[wid][lane][3] = a3;
        s_acc[wid][lane][4] = a4;
        s_acc[wid][lane][5] = a5;
        s_acc[wid][lane][6] = a6;
        s_acc[wid][lane][7] = a7;
    }
    __syncthreads();

    // ---- Deterministic fixed-order reduction + direct coalesced store.
    // Thread t handles grid point: row l = t>>3 (32 rows), x index i = t&7.
    int l = tid >> 3;
    int i = tid & 7;
    int rty = l & 7;
    int rtz = l >> 3;
    int g0 = (bz * TILE_Z + rtz) * (GRID_NX * GRID_NY)
           + (by * TILE_Y + rty) * GRID_NX
           + bx * TILE_X + i;

    float r = s_acc[0][l][i];
#pragma unroll
    for (int w = 1; w < NWARP; w++)
        r += s_acc[w][l][i];
    out[g0] = r;
}

// ---------------------------------------------------------------------------
// Launch. Inputs (metadata order): X[800*3] f32, aw[800*6] f32, bw[800*6] f32,
// elements[800] i32, C_expand[800] i32, real_grid[110592*3] f32 (unused).
// Output: density[110592] f32.
// ---------------------------------------------------------------------------
extern "C" void kernel_launch(void* const* d_in, const int* in_sizes, int n_in,
                              void* d_out, int out_size)
{
    const float* X        = (const float*)d_in[0];
    const float* aw       = (const float*)d_in[1];
    const float* bw       = (const float*)d_in[2];
    const int*   elements = (const int*)d_in[3];
    const int*   C_expand = (const int*)d_in[4];
    float*       out      = (float*)d_out;

    int n_atoms = in_sizes[3];
    int npairs  = n_atoms * NG;

    int nthreads = npairs * 48;
    build_tables<<<(nthreads + 255) / 256, 256>>>(X, aw, bw, elements,
                                                  C_expand, npairs);

    density_kernel<<<N_TILES, 256>>>(npairs, out);
}

// round 12
// speedup vs baseline: 1.1676x; 1.1676x over previous
#include <cuda_runtime.h>
#include <cuda_bf16.h>

// Problem constants (fixed by the reference)
#define GRID_NX   48
#define GRID_NY   48
#define GRID_NZ   48
#define N_GRID    (GRID_NX * GRID_NY * GRID_NZ)   // 110592
#define SPACING   0.5f
#define A_MAX     800
#define NG        6
#define MAX_PAIRS (A_MAX * NG)                    // 4800

// Cull threshold: drop pair for a tile when |c|*min_d2 > T  (contribution < 2^-18 * w)
#define T_CUT     18.0f

// Tile geometry: 8 x 8 x 4 grid points per tile (432 tiles)
#define TILE_X 8
#define TILE_Y 8
#define TILE_Z 4
#define NBX (GRID_NX / TILE_X)   // 6
#define NBY (GRID_NY / TILE_Y)   // 6
#define NBZ (GRID_NZ / TILE_Z)   // 12
#define N_TILES (NBX * NBY * NBZ)

#define NWARP  16                // pair-range partitions (one warp each, 512 thr)
#define CHUNK  32                // pairs culled per warp-chunk (one ballot)

// Scratch (__device__ globals, no allocation)
__device__ float4 g_cull[MAX_PAIRS];        // px, py, pz, d2cut (-1 => inactive)
// Separable 1-D tables. g_exp is PAIRED layout per x-tile:
//   g_exp[p][tile*8 + slot*2 + half] = Ex(tile*8 + slot + 4*half)
// so 4 consecutive ulonglongs per tile == (Ex(i), Ex(i+4)) for i=0..3,
// matching the packed accumulator layout accp_i = (x_i, x_{i+4}).
__device__ float g_exp[MAX_PAIRS][48];      // Ex, paired layout
__device__ float g_eyw[MAX_PAIRS][48];      // w * Ey
__device__ float g_ez [MAX_PAIRS][48];      // Ez

__device__ __forceinline__ float ex2f(float x) {
    float r;
    asm("ex2.approx.f32 %0, %1;" : "=f"(r) : "f"(x));
    return r;
}

// Packed f32x2 helpers (Blackwell)
__device__ __forceinline__ unsigned long long pk(float lo, float hi) {
    unsigned long long r;
    asm("mov.b64 %0, {%1, %2};" : "=l"(r) : "f"(lo), "f"(hi));
    return r;
}
__device__ __forceinline__ void unpk(float& lo, float& hi, unsigned long long v) {
    asm("mov.b64 {%0, %1}, %2;" : "=f"(lo), "=f"(hi) : "l"(v));
}
__device__ __forceinline__ unsigned long long fma2(unsigned long long a,
                                                   unsigned long long b,
                                                   unsigned long long c) {
    unsigned long long r;
    asm("fma.rn.f32x2 %0, %1, %2, %3;" : "=l"(r) : "l"(a), "l"(b), "l"(c));
    return r;
}

// ---------------------------------------------------------------------------
// Kernel 1: build cull table + separable 1-D exp tables.
// One thread per (pair, grid index i48): 3 EX2 per thread, fully parallel.
// ---------------------------------------------------------------------------
__global__ __launch_bounds__(256)
void build_tables(const float* __restrict__ X,
                  const float* __restrict__ aw,
                  const float* __restrict__ bw,
                  const int*   __restrict__ elements,
                  const int*   __restrict__ C_expand,
                  int npairs)
{
    const float LOG2E = 1.4426950408889634f;
    int t = blockIdx.x * 256 + threadIdx.x;
    int p   = t / 48;
    int i48 = t % 48;
    if (p >= npairs) return;
    int a = p / NG;

    float c = bw[p] * LOG2E;          // c < 0
    float w = aw[p];
    float px = X[a * 3 + 0];
    float py = X[a * 3 + 1];
    float pz = X[a * 3 + 2];

    float g = (float)i48 * SPACING;
    float dx = g - px, dy = g - py, dz = g - pz;

    // Ex in paired layout
    int tile = i48 >> 3, ii = i48 & 7;
    int slot = ii & 3, half = ii >> 2;
    g_exp[p][tile * 8 + slot * 2 + half] = ex2f(c * dx * dx);
    g_eyw[p][i48] = w * ex2f(c * dy * dy);
    g_ez [p][i48] = ex2f(c * dz * dz);

    if (i48 == 0) {
        bool act = (elements[a] != 5) && (C_expand[a] == 1);
        g_cull[p] = make_float4(px, py, pz, act ? (T_CUT / (-c)) : -1.0f);
    }
}

// ---------------------------------------------------------------------------
// Kernel 2: density. One 512-thread block per tile (16 warps); warp w handles
// pair sixteenth w independently: cull -> stage survivor slices into shared
// -> accumulate with PURE packed FMAs (no EX2 in the inner loop), survivor
// loop unrolled x2 for MLP. Deterministic fixed-order 16-way reduction.
//
// Shared memory OVERLAY: the survivor slice buffers (40 KB) are dead after
// the mainloop; the accumulator array (18 KB) aliases the same storage,
// separated by __syncthreads(). Keeps static shared at 40 KB (< 48 KB cap).
// ---------------------------------------------------------------------------
// Layout constants (floats)
#define EX_STRIDE   (CHUNK * 8)                  // per-warp Ex floats
#define EY_STRIDE   (CHUNK * 8)
#define EZ_STRIDE   (CHUNK * 4)
#define EX_BASE     0
#define EY_BASE     (NWARP * EX_STRIDE)          // 4096
#define EZ_BASE     (EY_BASE + NWARP * EY_STRIDE) // 8192
#define SMEM_FLOATS (EZ_BASE + NWARP * EZ_STRIDE) // 10240 floats = 40 KB
#define ACC_STRIDE  (32 * (TILE_X + 1))          // per-warp acc floats (288)

__global__ __launch_bounds__(512)
void density_kernel(int npairs, float* __restrict__ out)
{
    __shared__ __align__(16) float s_buf[SMEM_FLOATS];   // 40 KB, overlaid

    int tid  = threadIdx.x;
    int lane = tid & 31;
    int wid  = tid >> 5;
    int bid  = blockIdx.x;
    int bx = bid % NBX;
    int by = (bid / NBX) % NBY;
    int bz = bid / (NBX * NBY);

    float* s_ex = s_buf + EX_BASE + wid * EX_STRIDE;   // [CHUNK][8]
    float* s_ey = s_buf + EY_BASE + wid * EY_STRIDE;   // [CHUNK][8]
    float* s_ez = s_buf + EZ_BASE + wid * EZ_STRIDE;   // [CHUNK][4]

    // Tile AABB in real coordinates
    float x_lo = (float)(bx * TILE_X) * SPACING;
    float y_lo = (float)(by * TILE_Y) * SPACING;
    float z_lo = (float)(bz * TILE_Z) * SPACING;
    float x_hi = x_lo + (float)(TILE_X - 1) * SPACING;
    float y_hi = y_lo + (float)(TILE_Y - 1) * SPACING;
    float z_hi = z_lo + (float)(TILE_Z - 1) * SPACING;

    // This lane's x-row: lane -> (ty in 0..7, tz in 0..3)
    int ty = lane & 7;
    int tz = lane >> 3;

    // This warp's pair range
    int p_beg = (npairs * wid) / NWARP;
    int p_end = (npairs * (wid + 1)) / NWARP;

    // Packed accumulators: accp[i] = (sum @ x_i, sum @ x_{i+4})
    unsigned long long accp0 = 0ull, accp1 = 0ull, accp2 = 0ull, accp3 = 0ull;

    for (int c0 = p_beg; c0 < p_end; c0 += CHUNK) {
        int cend = p_end - c0;
        if (cend > CHUNK) cend = CHUNK;

        // ---- Cull one 32-pair chunk + stage survivor slices into shared
        int j = c0 + lane;
        bool sv = false;
        if (lane < cend) {
            float4 cd = g_cull[j];
            float dx = fmaxf(fmaxf(x_lo - cd.x, cd.x - x_hi), 0.0f);
            float dy = fmaxf(fmaxf(y_lo - cd.y, cd.y - y_hi), 0.0f);
            float dz = fmaxf(fmaxf(z_lo - cd.z, cd.z - z_hi), 0.0f);
            float md2 = fmaf(dx, dx, fmaf(dy, dy, dz * dz));
            sv = (md2 <= cd.w);
        }
        unsigned m = __ballot_sync(0xffffffffu, sv);
        int nsurv = __popc(m);
        if (sv) {
            int pos = __popc(m & ((1u << lane) - 1u));
            const float4* ex = reinterpret_cast<const float4*>(&g_exp[j][bx * 8]);
            const float4* ey = reinterpret_cast<const float4*>(&g_eyw[j][by * 8]);
            const float4* ez = reinterpret_cast<const float4*>(&g_ez [j][bz * 4]);
            reinterpret_cast<float4*>(s_ex + pos * 8)[0] = ex[0];
            reinterpret_cast<float4*>(s_ex + pos * 8)[1] = ex[1];
            reinterpret_cast<float4*>(s_ey + pos * 8)[0] = ey[0];
            reinterpret_cast<float4*>(s_ey + pos * 8)[1] = ey[1];
            reinterpret_cast<float4*>(s_ez + pos * 4)[0] = ez[0];
        }
        __syncwarp();

        // ---- Accumulate: pure packed FMAs, unrolled x2 for MLP
        int s = 0;
        for (; s + 2 <= nsurv; s += 2) {
            float eyzA = s_ey[s * 8 + ty]       * s_ez[s * 4 + tz];
            float eyzB = s_ey[(s + 1) * 8 + ty] * s_ez[(s + 1) * 4 + tz];
            unsigned long long eA = pk(eyzA, eyzA);
            unsigned long long eB = pk(eyzB, eyzB);
            const unsigned long long* xA =
                reinterpret_cast<const unsigned long long*>(s_ex + s * 8);
            const unsigned long long* xB =
                reinterpret_cast<const unsigned long long*>(s_ex + (s + 1) * 8);
            accp0 = fma2(xA[0], eA, accp0);
            accp1 = fma2(xA[1], eA, accp1);
            accp2 = fma2(xA[2], eA, accp2);
            accp3 = fma2(xA[3], eA, accp3);
            accp0 = fma2(xB[0], eB, accp0);
            accp1 = fma2(xB[1], eB, accp1);
            accp2 = fma2(xB[2], eB, accp2);
            accp3 = fma2(xB[3], eB, accp3);
        }
        if (s < nsurv) {
            float eyz = s_ey[s * 8 + ty] * s_ez[s * 4 + tz];
            unsigned long long e2 = pk(eyz, eyz);
            const unsigned long long* xp =
                reinterpret_cast<const unsigned long long*>(s_ex + s * 8);
            accp0 = fma2(xp[0], e2, accp0);
            accp1 = fma2(xp[1], e2, accp1);
            accp2 = fma2(xp[2], e2, accp2);
            accp3 = fma2(xp[3], e2, accp3);
        }
        __syncwarp();   // protect this warp's shared slices before refill
    }

    // ---- All survivor-slice reads done; retire slice buffers, alias as acc.
    __syncthreads();
    float* s_acc = s_buf;                        // [NWARP][32][TILE_X+1]
    {
        float* row = s_acc + wid * ACC_STRIDE + lane * (TILE_X + 1);
        float a0, a4, a1, a5, a2, a6, a3, a7;
        unpk(a0, a4, accp0);
        unpk(a1, a5, accp1);
        unpk(a2, a6, accp2);
        unpk(a3, a7, accp3);
        row[0] = a0; row[1] = a1; row[2] = a2; row[3] = a3;
        row[4] = a4; row[5] = a5; row[6] = a6; row[7] = a7;
    }
    __syncthreads();

    // ---- Deterministic fixed-order 16-way reduction + coalesced store.
    // First 256 threads: row l = t>>3 (32 rows), x index i = t&7.
    if (tid < 256) {
        int l = tid >> 3;
        int i = tid & 7;
        int rty = l & 7;
        int rtz = l >> 3;
        int g0 = (bz * TILE_Z + rtz) * (GRID_NX * GRID_NY)
               + (by * TILE_Y + rty) * GRID_NX
               + bx * TILE_X + i;

        float r = s_acc[l * (TILE_X + 1) + i];
#pragma unroll
        for (int w = 1; w < NWARP; w++)
            r += s_acc[w * ACC_STRIDE + l * (TILE_X + 1) + i];
        out[g0] = r;
    }
}

// ---------------------------------------------------------------------------
// Launch. Inputs (metadata order): X[800*3] f32, aw[800*6] f32, bw[800*6] f32,
// elements[800] i32, C_expand[800] i32, real_grid[110592*3] f32 (unused).
// Output: density[110592] f32.
// ---------------------------------------------------------------------------
extern "C" void kernel_launch(void* const* d_in, const int* in_sizes, int n_in,
                              void* d_out, int out_size)
{
    const float* X        = (const float*)d_in[0];
    const float* aw       = (const float*)d_in[1];
    const float* bw       = (const float*)d_in[2];
    const int*   elements = (const int*)d_in[3];
    const int*   C_expand = (const int*)d_in[4];
    float*       out      = (float*)d_out;

    int n_atoms = in_sizes[3];
    int npairs  = n_atoms * NG;

    int nthreads = npairs * 48;
    build_tables<<<(nthreads + 255) / 256, 256>>>(X, aw, bw, elements,
                                                  C_expand, npairs);

    density_kernel<<<N_TILES, 512>>>(npairs, out);
}